// round 1
// baseline (speedup 1.0000x reference)
#include <cuda_runtime.h>
#include <math.h>

// ---------------------------------------------------------------------------
// ClassicalMappedQRNN: B independent chains, sequential over S.
//   phi = atan(x); e = (cos(phi/2), 0, sin(phi/2), 0)
//   h'  = Rx e + Rz h ; h' /= ||h'||
// Output per chain: z = h0^2 + h1^2 - h2^2 - h3^2.
//
// Key identities used (alpha = beta = pi/2 fast path):
//   cos(phi) = r = 1/sqrt(1+x^2)
//   Rx e = v = (1/sqrt2)*(c, -s, s, c), c=cos(phi/2), s=sin(phi/2)
//   Rz h = (1/sqrt2)*(h0-h1, h0+h1, h2+h3, h3-h2)
//   ||Rz h|| = ||v|| = 1  =>  ||h'||^2 = 2 + 2 <Rz h, v>
// State g (unnormalized, direction == h) with K = 1/(sqrt2*||g||):
//   w  = (g0-g1, g0+g1, g2+g3, g3-g2)          (unscaled rotation)
//   g' = K*w + v
//   m' = 4 + K*(w . 4v)      ;  K' = rsqrt(m')
// The K chain is fma(4) + MUFU.RSQ(16) = 20 cyc/step; ~24 instrs/step.
// ---------------------------------------------------------------------------

__device__ __forceinline__ float rsqa(float x) {
    float y; asm("rsqrt.approx.f32 %0, %1;" : "=f"(y) : "f"(x)); return y;
}
__device__ __forceinline__ float sqa(float x) {
    float y; asm("sqrt.approx.f32 %0, %1;" : "=f"(y) : "f"(x)); return y;
}

template <bool FAST>
struct Runner {
    float g0, g1, g2, g3, K;
    float ca, sa, cbs, sbs;   // generic-path constants (cbs = cb/sqrt2, sbs = sb/sqrt2)

    __device__ __forceinline__ void init(float xv) {
        float t = fmaf(xv, xv, 1.0f);
        float r = rsqa(t);                 // cos(phi)
        if (FAST) {
            float ch  = sqa(fmaf(r,  0.25f, 0.25f));   // (1/sqrt2) cos(phi/2)
            float shm = sqa(fmaf(r, -0.25f, 0.25f));
            float sh  = copysignf(shm, xv);            // (1/sqrt2) sin(phi/2)
            g0 = ch; g1 = -sh; g2 = sh; g3 = ch;       // g = v, ||g|| ~ 1
            float ss = (g0*g0 + g1*g1) + (g2*g2 + g3*g3);
            K = rsqa(ss + ss);                          // 1/(sqrt2*||g||)
        } else {
            float c   = sqa(fmaf(r,  0.5f, 0.5f));
            float smv = sqa(fmaf(r, -0.5f, 0.5f));
            float s   = copysignf(smv, xv);
            g0 = ca * c; g1 = -(sa * s); g2 = ca * s; g3 = sa * c;
            float ss = (g0*g0 + g1*g1) + (g2*g2 + g3*g3);
            K = rsqa(0.5f * ss);                        // rho = sqrt2/||g||
        }
    }

    __device__ __forceinline__ void step(float xv) {
        float t = fmaf(xv, xv, 1.0f);
        float r = rsqa(t);
        if (FAST) {
            float ch  = sqa(fmaf(r,  0.25f, 0.25f));
            float shm = sqa(fmaf(r, -0.25f, 0.25f));
            float sh  = copysignf(shm, xv);
            float c8  = 4.0f * ch;
            float s8  = 4.0f * sh;
            float w0 = g0 - g1, w1 = g0 + g1, w2 = g2 + g3, w3 = g3 - g2;
            // d = w . (4v),  v = (ch, -sh, sh, ch)
            float q0 = w0 * c8;
            float q1 = fmaf(w1, -s8, q0);
            float q2 = w2 * s8;
            float q3 = fmaf(w3, c8, q2);
            float d  = q1 + q3;
            float n0 = fmaf(K, w0, ch);
            float n1 = fmaf(K, w1, -sh);
            float n2 = fmaf(K, w2, sh);
            float n3 = fmaf(K, w3, ch);
            float m  = fmaf(K, d, 4.0f);
            m = fmaxf(m, 1e-20f);          // guard: rounding could dip below 0 at exact anti-alignment
            K = rsqa(m);
            g0 = n0; g1 = n1; g2 = n2; g3 = n3;
        } else {
            float c   = sqa(fmaf(r,  0.5f, 0.5f));
            float smv = sqa(fmaf(r, -0.5f, 0.5f));
            float s   = copysignf(smv, xv);
            float v0 = ca * c, v1 = -(sa * s), v2 = ca * s, v3 = sa * c;
            // w = (1/sqrt2) Rz g  via pre-scaled constants
            float w0 = fmaf(cbs, g0, -(sbs * g1));
            float w1 = fmaf(sbs, g0,  (cbs * g1));
            float w2 = fmaf(cbs, g2,  (sbs * g3));
            float w3 = fmaf(cbs, g3, -(sbs * g2));
            float q0 = w0 * v0;
            float q1 = fmaf(w1, v1, q0);
            float q2 = w2 * v2;
            float q3 = fmaf(w3, v3, q2);
            float d  = q1 + q3;
            float n0 = fmaf(K, w0, v0);
            float n1 = fmaf(K, w1, v1);
            float n2 = fmaf(K, w2, v2);
            float n3 = fmaf(K, w3, v3);
            float m  = fmaf(K, d, 1.0f);   // sigma' = 1 + rho <w~, v>
            m = fmaxf(m, 1e-20f);
            K = rsqa(m);
            g0 = n0; g1 = n1; g2 = n2; g3 = n3;
        }
    }

    __device__ __forceinline__ void renorm() {
        float ss = (g0*g0 + g1*g1) + (g2*g2 + g3*g3);
        K = FAST ? rsqa(ss + ss) : rsqa(0.5f * ss);
    }

    template <bool FIRST>
    __device__ __forceinline__ void chunk(const float4 (&buf)[8]) {
        #pragma unroll
        for (int i = 0; i < 8; i++) {
            float4 f = buf[i];
            if (FIRST && i == 0) init(f.x); else step(f.x);
            step(f.y); step(f.z); step(f.w);
        }
        renorm();   // exact rescale every 32 steps: kills approx-rsqrt drift
    }
};

template <bool FAST>
__device__ __forceinline__ void run_chain(const float* __restrict__ xrow,
                                          float* __restrict__ outb, int S,
                                          float ca, float sa, float cbs, float sbs) {
    Runner<FAST> R;
    R.ca = ca; R.sa = sa; R.cbs = cbs; R.sbs = sbs;
    const float4* xp = reinterpret_cast<const float4*>(xrow);

    float4 bufA[8], bufB[8];
    #pragma unroll
    for (int i = 0; i < 8; i++) bufA[i] = xp[i];
    #pragma unroll
    for (int i = 0; i < 8; i++) bufB[i] = xp[8 + i];

    const int nch = S >> 5;                       // chunks of 32 elems; nch even
    R.template chunk<true>(bufA);                 // chunk 0

    #pragma unroll 1
    for (int cc = 1; cc + 1 < nch; cc += 2) {
        #pragma unroll
        for (int i = 0; i < 8; i++) bufA[i] = xp[(cc + 1) * 8 + i];   // prefetch cc+1
        R.template chunk<false>(bufB);                                 // process cc
        #pragma unroll
        for (int i = 0; i < 8; i++) bufB[i] = xp[(cc + 2) * 8 + i];   // prefetch cc+2
        R.template chunk<false>(bufA);                                 // process cc+1
    }
    R.template chunk<false>(bufB);                // chunk nch-1

    float a01 = R.g0 * R.g0 + R.g1 * R.g1;
    float a23 = R.g2 * R.g2 + R.g3 * R.g3;
    *outb = (a01 - a23) / (a01 + a23);            // z = (h0^2+h1^2) - (h2^2+h3^2)
}

// Straightforward fallback for shapes not multiple of 64 (safety net).
__device__ void run_simple(const float* __restrict__ xrow, float* __restrict__ outb,
                           int S, float ca, float sa, float cb, float sb) {
    float h0 = 0.f, h1 = 0.f, h2 = 0.f, h3 = 0.f;
    for (int t = 0; t < S; t++) {
        float xv = xrow[t];
        float phi = atanf(xv);
        float c = cosf(0.5f * phi);
        float s = sinf(0.5f * phi);
        float u0 = ca * c + cb * h0 - sb * h1;
        float u1 = -(sa * s) + sb * h0 + cb * h1;
        float u2 = ca * s + cb * h2 + sb * h3;
        float u3 = sa * c - sb * h2 + cb * h3;
        float ss = u0*u0 + u1*u1 + u2*u2 + u3*u3;
        float rn = rsqrtf(ss);
        h0 = u0 * rn; h1 = u1 * rn; h2 = u2 * rn; h3 = u3 * rn;
    }
    *outb = (h0*h0 + h1*h1) - (h2*h2 + h3*h3);
}

__global__ void __launch_bounds__(64, 1)
qrnn_kernel(const float* __restrict__ x, const float* __restrict__ pa,
            const float* __restrict__ pb, float* __restrict__ out, int B, int S) {
    int b = blockIdx.x * blockDim.x + threadIdx.x;
    if (b >= B) return;

    float alpha = __ldg(pa);
    float beta  = __ldg(pb);
    const float PIO2  = 1.57079632679489662f;
    const float INVS2 = 0.70710678118654752f;
    float ca = cosf(0.5f * alpha), sa = sinf(0.5f * alpha);
    float cb = cosf(0.5f * beta),  sb = sinf(0.5f * beta);
    bool fast = (fabsf(alpha - PIO2) < 1e-5f) && (fabsf(beta - PIO2) < 1e-5f);

    const float* xrow = x + (size_t)b * (size_t)S;
    float* outb = out + b;

    if (S >= 64 && (S % 64) == 0) {
        if (fast) run_chain<true >(xrow, outb, S, ca, sa, cb * INVS2, sb * INVS2);
        else      run_chain<false>(xrow, outb, S, ca, sa, cb * INVS2, sb * INVS2);
    } else {
        run_simple(xrow, outb, S, ca, sa, cb, sb);
    }
}

extern "C" void kernel_launch(void* const* d_in, const int* in_sizes, int n_in,
                              void* d_out, int out_size) {
    const float* x  = (const float*)d_in[0];
    const float* pa = (const float*)d_in[1];
    const float* pb = (const float*)d_in[2];
    float* out = (float*)d_out;

    int B = out_size;                 // 8192
    int S = in_sizes[0] / B;          // 4096

    int grid = (B + 63) / 64;         // 128 blocks x 64 threads:
    qrnn_kernel<<<grid, 64>>>(x, pa, pb, out, B, S);   // <=1 block/SM, 1 warp/SMSP
}

// round 3
// speedup vs baseline: 1.6521x; 1.6521x over previous
#include <cuda_runtime.h>
#include <cstdint>
#include <math.h>

// ---------------------------------------------------------------------------
// ClassicalMappedQRNN: B=8192 independent chains, sequential over S=4096.
//   phi = atan(x); e = (cos(phi/2), 0, sin(phi/2), 0)
//   h'  = Rx e + Rz h ; h' /= ||h'||        (alpha = beta = pi/2 in practice)
// Output per chain: z = h0^2 + h1^2 - h2^2 - h3^2.
//
// Fast-path algebra (alpha = beta = pi/2):
//   r  = cos(phi) = 1/sqrt(1+x^2)
//   (ch, sh) = (cos(phi/2), sin(phi/2))/sqrt2  via  q = rsqrt(4(1+r)):
//       ch = (1+r) q,   sh = x r q            (2 MUFU, sign free)
//   v  = (ch, -sh, sh, ch), ||v|| = 1
//   w  = (g0-g1, g0+g1, g2+g3, g3-g2)   (unscaled Rz of state g)
//   g' = K w + v,   K = 1/(sqrt2 ||g||)  =>  ||K w|| = 1
//   m  = 4 + K * (w . 4v) = 4(1 + K<w,v>);  K' = rsqrt(m) = 1/(sqrt2 ||g'||)
// Serial chain per step: FMA + FMNMX + MUFU.RSQ (~25 cyc). 3 MUFU/step.
// Input streamed via cp.async double buffer in smem (per-thread groups,
// no block barriers needed: each thread consumes only its own bytes).
// ---------------------------------------------------------------------------

__device__ __forceinline__ float rsqa(float x) {
    float y; asm("rsqrt.approx.f32 %0, %1;" : "=f"(y) : "f"(x)); return y;
}

__device__ __forceinline__ void cp_async16(uint32_t dst_smem, const void* src) {
    asm volatile("cp.async.cg.shared.global [%0], [%1], 16;"
                 :: "r"(dst_smem), "l"(src));
}
__device__ __forceinline__ void cp_commit() {
    asm volatile("cp.async.commit_group;");
}
template <int N>
__device__ __forceinline__ void cp_wait() {
    asm volatile("cp.async.wait_group %0;" :: "n"(N));
}

#define CHUNK 32                 // steps per smem chunk
#define TPB   64                 // threads per block (2 warps -> SMSP 0,1)
#define ROWF  36                 // padded floats per thread row (bank spread)

template <bool FAST>
struct Runner {
    float g0, g1, g2, g3, K;
    float caf, saf, cbs, sbs;    // generic path constants (pre-scaled)

    // trig: returns (ch, sh) = (cos(phi/2), sin(phi/2)) / sqrt2
    __device__ __forceinline__ void trig(float xv, float& ch, float& sh) {
        float t  = fmaf(xv, xv, 1.0f);
        float r  = rsqa(t);                  // cos(phi)
        float e  = fmaf(r, 4.0f, 4.0f);      // 4(1+r)
        float q  = rsqa(e);
        float rq = r * q;
        ch = q + rq;                         // (1+r) q
        sh = xv * rq;                        // x r q   (sign included)
    }

    __device__ __forceinline__ void init(float xv) {
        float ch, sh;
        trig(xv, ch, sh);
        if (FAST) {
            g0 = ch; g1 = -sh; g2 = sh; g3 = ch;     // g = v, ||g|| = 1
            K  = 0.70710678118654752f;                // 1/(sqrt2*||g||)
        } else {
            // v = (ca*c, -sa*s, ca*s, sa*c) with c = sqrt2*ch, s = sqrt2*sh
            g0 = caf * ch; g1 = -(saf * sh); g2 = caf * sh; g3 = saf * ch;
            float ss = (g0*g0 + g1*g1) + (g2*g2 + g3*g3);
            K = rsqa(0.5f * ss);                      // sqrt2/||g||
        }
    }

    __device__ __forceinline__ void step(float xv) {
        float ch, sh;
        trig(xv, ch, sh);
        if (FAST) {
            float c4 = 4.0f * ch;
            float s4 = 4.0f * sh;
            float w0 = g0 - g1, w1 = g0 + g1, w2 = g2 + g3, w3 = g3 - g2;
            float a  = w0 + w3;
            float bb = w2 - w1;
            float d  = fmaf(bb, s4, a * c4);          // w . 4v
            float n0 = fmaf(K, w0,  ch);
            float n1 = fmaf(K, w1, -sh);
            float n2 = fmaf(K, w2,  sh);
            float n3 = fmaf(K, w3,  ch);
            float m  = fmaf(K, d, 4.0f);
            K  = rsqa(fmaxf(m, 1e-12f));
            g0 = n0; g1 = n1; g2 = n2; g3 = n3;
        } else {
            float v0 = caf * ch, v1 = -(saf * sh), v2 = caf * sh, v3 = saf * ch;
            // w = (1/sqrt2) Rz g via pre-scaled rotation constants; ||w|| = ||g||/sqrt2
            float w0 = fmaf(cbs, g0, -(sbs * g1));
            float w1 = fmaf(sbs, g0,  (cbs * g1));
            float w2 = fmaf(cbs, g2,  (sbs * g3));
            float w3 = fmaf(cbs, g3, -(sbs * g2));
            float q0 = w0 * v0;
            float q1 = fmaf(w1, v1, q0);
            float q2 = w2 * v2;
            float q3 = fmaf(w3, v3, q2);
            float d  = q1 + q3;                       // <w, v>
            float n0 = fmaf(K, w0, v0);               // g' = K w + v, ||Kw|| = 1
            float n1 = fmaf(K, w1, v1);
            float n2 = fmaf(K, w2, v2);
            float n3 = fmaf(K, w3, v3);
            // ||g'||^2 = 1 + 2K d + 1;  K' = rsqrt(0.5*||g'||^2) = rsqrt(1 + K d)
            float m  = fmaf(K, d, 1.0f);
            K  = rsqa(fmaxf(m, 1e-12f));
            g0 = n0; g1 = n1; g2 = n2; g3 = n3;
        }
    }

    __device__ __forceinline__ void renorm() {
        float ss = (g0*g0 + g1*g1) + (g2*g2 + g3*g3);
        K = rsqa(ss + ss);           // exact 1/(sqrt2 ||g||), both paths
    }

    template <bool FIRST>
    __device__ __forceinline__ void chunk(const float* __restrict__ sb) {
        #pragma unroll
        for (int i = 0; i < CHUNK / 4; i++) {
            float4 f = *reinterpret_cast<const float4*>(sb + i * 4);
            if (FIRST && i == 0) init(f.x); else step(f.x);
            step(f.y); step(f.z); step(f.w);
        }
        renorm();   // exact rescale every CHUNK steps: kills approx-rsqrt drift
    }
};

__shared__ float sbuf[2 * TPB * ROWF];

__device__ __forceinline__ void issue_chunk(const float* __restrict__ xrow,
                                            int c, int buf, int tid) {
    uint32_t dst = (uint32_t)__cvta_generic_to_shared(
        &sbuf[buf * (TPB * ROWF) + tid * ROWF]);
    const float* src = xrow + c * CHUNK;
    #pragma unroll
    for (int i = 0; i < CHUNK / 4; i++)
        cp_async16(dst + i * 16, src + i * 4);
    cp_commit();
}

template <bool FAST>
__device__ __forceinline__ void run_chain(const float* __restrict__ xrow,
                                          float* __restrict__ outb, int S,
                                          float caf, float saf, float cbs, float sbs,
                                          int tid) {
    Runner<FAST> R;
    R.caf = caf; R.saf = saf; R.cbs = cbs; R.sbs = sbs;

    const int nch = S / CHUNK;           // >= 3 guaranteed by caller
    issue_chunk(xrow, 0, 0, tid);
    issue_chunk(xrow, 1, 1, tid);

    const float* sb0 = &sbuf[tid * ROWF];
    const float* sb1 = &sbuf[TPB * ROWF + tid * ROWF];

    cp_wait<1>();                        // chunk 0 landed
    R.template chunk<true>(sb0);
    issue_chunk(xrow, 2, 0, tid);

    #pragma unroll 1
    for (int c = 1; c < nch; c++) {
        if (c + 1 < nch) cp_wait<1>(); else cp_wait<0>();
        R.template chunk<false>((c & 1) ? sb1 : sb0);
        if (c + 2 < nch) issue_chunk(xrow, c + 2, c & 1, tid);
    }

    float a01 = R.g0 * R.g0 + R.g1 * R.g1;
    float a23 = R.g2 * R.g2 + R.g3 * R.g3;
    *outb = (a01 - a23) / (a01 + a23);
}

// Straightforward fallback for odd shapes (safety net).
__device__ void run_simple(const float* __restrict__ xrow, float* __restrict__ outb,
                           int S, float ca, float sa, float cb, float sb) {
    float h0 = 0.f, h1 = 0.f, h2 = 0.f, h3 = 0.f;
    for (int t = 0; t < S; t++) {
        float xv = xrow[t];
        float phi = atanf(xv);
        float c = cosf(0.5f * phi);
        float s = sinf(0.5f * phi);
        float u0 = ca * c + cb * h0 - sb * h1;
        float u1 = -(sa * s) + sb * h0 + cb * h1;
        float u2 = ca * s + cb * h2 + sb * h3;
        float u3 = sa * c - sb * h2 + cb * h3;
        float ss = u0*u0 + u1*u1 + u2*u2 + u3*u3;
        float rn = rsqrtf(ss);
        h0 = u0 * rn; h1 = u1 * rn; h2 = u2 * rn; h3 = u3 * rn;
    }
    *outb = (h0*h0 + h1*h1) - (h2*h2 + h3*h3);
}

__global__ void __launch_bounds__(TPB, 1)
qrnn_kernel(const float* __restrict__ x, const float* __restrict__ pa,
            const float* __restrict__ pb, float* __restrict__ out, int B, int S) {
    int tid = threadIdx.x;
    int b = blockIdx.x * TPB + tid;
    if (b >= B) return;

    float alpha = __ldg(pa);
    float beta  = __ldg(pb);
    const float PIO2  = 1.57079632679489662f;
    const float SQRT2 = 1.41421356237309505f;
    const float INVS2 = 0.70710678118654752f;
    float ca = cosf(0.5f * alpha), sa = sinf(0.5f * alpha);
    float cb = cosf(0.5f * beta),  sb = sinf(0.5f * beta);
    bool fast = (fabsf(alpha - PIO2) < 1e-5f) && (fabsf(beta - PIO2) < 1e-5f);

    const float* xrow = x + (size_t)b * (size_t)S;
    float* outb = out + b;

    if (S >= 96 && (S % CHUNK) == 0) {
        if (fast) run_chain<true >(xrow, outb, S, ca * SQRT2, sa * SQRT2,
                                   cb * INVS2, sb * INVS2, tid);
        else      run_chain<false>(xrow, outb, S, ca * SQRT2, sa * SQRT2,
                                   cb * INVS2, sb * INVS2, tid);
    } else {
        run_simple(xrow, outb, S, ca, sa, cb, sb);
    }
}

extern "C" void kernel_launch(void* const* d_in, const int* in_sizes, int n_in,
                              void* d_out, int out_size) {
    const float* x  = (const float*)d_in[0];
    const float* pa = (const float*)d_in[1];
    const float* pb = (const float*)d_in[2];
    float* out = (float*)d_out;

    int B = out_size;                 // 8192
    int S = in_sizes[0] / B;          // 4096

    int grid = (B + TPB - 1) / TPB;   // 128 blocks x 64 threads:
    qrnn_kernel<<<grid, TPB>>>(x, pa, pb, out, B, S);   // 1 block/SM, 1 warp/SMSP
}